// round 10
// baseline (speedup 1.0000x reference)
#include <cuda_runtime.h>
#include <cuda_bf16.h>

// Problem constants (fixed-shape problem)
#define NPTS   400000
#define CIN    32
#define COUT   32
#define KTAPS  27

#define BLOCK1 128          // 4 warps
#define WARPS1 4
#define PW     32           // points per warp
#define PTSBLK (WARPS1*PW)  // 128 points per block
#define NBLK1  (NPTS/PTSBLK) // 3125 exactly

#define TOTAL4 (NPTS*COUT/4)
#define NBLK3  (TOTAL4/256)

typedef unsigned long long u64;

// Scratch (static device memory — no allocations)
__device__ float g_conv[(size_t)NPTS * COUT];
__device__ float g_wT[KTAPS * CIN * COUT];        // transposed weights [k][co][ci]
__device__ float g_part[(size_t)NBLK1 * 64];
__device__ float g_coef[64];
__device__ int   g_maskmode;   // 0 = uint8 mask, 1 = int32 mask

// packed f32x2 helpers (sm_103a FFMA2 — only reachable via PTX)
__device__ __forceinline__ u64 fma2(u64 a, u64 b, u64 c) {
    u64 d; asm("fma.rn.f32x2 %0, %1, %2, %3;" : "=l"(d) : "l"(a), "l"(b), "l"(c)); return d;
}
__device__ __forceinline__ u64 add2(u64 a, u64 b) {
    u64 d; asm("add.rn.f32x2 %0, %1, %2;" : "=l"(d) : "l"(a), "l"(b)); return d;
}
__device__ __forceinline__ float hsum2(u64 a) {
    float2 f = *(float2*)&a; return f.x + f.y;
}

// ---------------------------------------------------------------------------
// K0a: detect storage width of nbr_mask (int32 {0,1} vs packed uint8 bools)
// ---------------------------------------------------------------------------
__global__ void detect_mask_kernel(const unsigned int* __restrict__ m)
{
    __shared__ int found;
    if (threadIdx.x == 0) found = 0;
    __syncthreads();
    int f = 0;
    for (int i = threadIdx.x; i < 4096; i += blockDim.x)
        if (m[i] > 1u) f = 1;
    if (f) atomicOr(&found, 1);
    __syncthreads();
    if (threadIdx.x == 0) g_maskmode = found ? 0 : 1;
}

// ---------------------------------------------------------------------------
// K0b: transpose weights w[k][ci][co] -> wT[k][co][ci] (27k elements, one-off)
// ---------------------------------------------------------------------------
__global__ void transpose_w_kernel(const float* __restrict__ w, float* __restrict__ wT)
{
    const int i = blockIdx.x * 256 + threadIdx.x;
    if (i < KTAPS * CIN * COUT) {
        const int k  = i >> 10;
        const int r  = i & 1023;
        const int ci = r >> 5;
        const int co = r & 31;
        wT[k * 1024 + co * 32 + ci] = w[i];
    }
}

// ---------------------------------------------------------------------------
// K1: gather-conv, set-bit inner loop, f32x2 packed FMA, 2 taps / iteration.
// lane = c_out; warp owns 32 points. Per tap k: ballot over coalesced meta;
// weights for (k,lane) = 8 LDG.128 of contiguous wT row (f32x2-pair aligned
// with feature row pairs). Inner loop pulls TWO set bits at a time: both
// rows' 8 uniform-address LDG.128 issue before either FMA chain consumes
// them (halved latency exposure + independent ILP chains).
// ---------------------------------------------------------------------------
__global__ __launch_bounds__(BLOCK1)
void conv_kernel(const float* __restrict__ feat,
                 const float* __restrict__ wT,
                 const int*   __restrict__ nidx,
                 const unsigned char* __restrict__ nmask8,
                 const int*   __restrict__ nmask32,
                 float* __restrict__ convout,
                 float* __restrict__ partials)
{
    // sacc[point_in_block][lane]: each thread exclusively owns column lane.
    __shared__ float sacc[PTSBLK * 32];
    __shared__ float red[2][WARPS1][COUT];

    const int tid  = threadIdx.x;
    const int wid  = tid >> 5;
    const int lane = tid & 31;
    const int n0   = blockIdx.x * PTSBLK + wid * PW;
    const int maskmode = g_maskmode;

#pragma unroll
    for (int p = 0; p < PW; p++) sacc[(wid * PW + p) * 32 + lane] = 0.0f;

    // meta for tap 0 (each lane carries one of the warp's 32 points)
    bool mv;
    int  idxv;
    {
        const size_t j = (size_t)(n0 + lane);
        mv   = maskmode ? (nmask32[j] != 0) : (nmask8[j] != 0);
        idxv = nidx[j];
    }

    for (int k = 0; k < KTAPS; k++) {
        const unsigned vm = __ballot_sync(0xffffffffu, mv);
        const int idxc = idxv;

        // prefetch meta for tap k+1
        if (k + 1 < KTAPS) {
            const size_t j = (size_t)(k + 1) * NPTS + (n0 + lane);
            mv   = maskmode ? (nmask32[j] != 0) : (nmask8[j] != 0);
            idxv = nidx[j];
        }

        if (vm == 0u) continue;   // warp-uniform

        // my weight row for this tap: wT[k][lane][0..31], 8 x LDG.128 -> 16 f32x2
        const ulonglong2* wrow = (const ulonglong2*)(wT + k * 1024 + lane * 32);
        u64 wp[16];
#pragma unroll
        for (int j = 0; j < 8; j++) {
            const ulonglong2 v = __ldg(wrow + j);
            wp[2*j] = v.x; wp[2*j+1] = v.y;
        }

        unsigned rem = vm;
        while (rem) {
            const int p0 = __ffs(rem) - 1; rem &= rem - 1u;
            int p1 = -1;
            if (rem) { p1 = __ffs(rem) - 1; rem &= rem - 1u; }

            const int gi0 = __shfl_sync(0xffffffffu, idxc, p0);
            const int gi1 = __shfl_sync(0xffffffffu, idxc, p1 >= 0 ? p1 : p0);

            const ulonglong2* r0 = (const ulonglong2*)(feat + (size_t)gi0 * CIN);
            const ulonglong2* r1 = (const ulonglong2*)(feat + (size_t)gi1 * CIN);

            // batch both rows' loads (uniform addr -> 1 txn each)
            u64 a[16], b[16];
#pragma unroll
            for (int j = 0; j < 8; j++) {
                const ulonglong2 v = __ldg(r0 + j);
                a[2*j] = v.x; a[2*j+1] = v.y;
            }
#pragma unroll
            for (int j = 0; j < 8; j++) {
                const ulonglong2 v = __ldg(r1 + j);
                b[2*j] = v.x; b[2*j+1] = v.y;
            }

            // dot0: 16 packed FMAs into 4 chains (depth 4)
            u64 c0 = 0, c1 = 0, c2 = 0, c3 = 0;
#pragma unroll
            for (int j = 0; j < 4; j++) {
                c0 = fma2(a[4*j+0], wp[4*j+0], c0);
                c1 = fma2(a[4*j+1], wp[4*j+1], c1);
                c2 = fma2(a[4*j+2], wp[4*j+2], c2);
                c3 = fma2(a[4*j+3], wp[4*j+3], c3);
            }
            const float dot0 = hsum2(add2(add2(c0, c1), add2(c2, c3)));
            sacc[(wid * PW + p0) * 32 + lane] += dot0;

            if (p1 >= 0) {   // warp-uniform
                u64 d0 = 0, d1 = 0, d2 = 0, d3 = 0;
#pragma unroll
                for (int j = 0; j < 4; j++) {
                    d0 = fma2(b[4*j+0], wp[4*j+0], d0);
                    d1 = fma2(b[4*j+1], wp[4*j+1], d1);
                    d2 = fma2(b[4*j+2], wp[4*j+2], d2);
                    d3 = fma2(b[4*j+3], wp[4*j+3], d3);
                }
                const float dot1 = hsum2(add2(add2(d0, d1), add2(d2, d3)));
                sacc[(wid * PW + p1) * 32 + lane] += dot1;
            }
        }
    }

    // write conv output (coalesced) + per-block partial sums for batchnorm
    float s = 0.0f, s2 = 0.0f;
#pragma unroll
    for (int p = 0; p < PW; p++) {
        const float v = sacc[(wid * PW + p) * 32 + lane];
        convout[(size_t)(n0 + p) * COUT + lane] = v;
        s  += v;
        s2 += v * v;
    }
    red[0][wid][lane] = s;
    red[1][wid][lane] = s2;
    __syncthreads();
    if (wid == 0) {
        float a = 0.0f, b = 0.0f;
#pragma unroll
        for (int w = 0; w < WARPS1; w++) { a += red[0][w][lane]; b += red[1][w][lane]; }
        partials[(size_t)blockIdx.x * 64 + lane]      = a;
        partials[(size_t)blockIdx.x * 64 + 32 + lane] = b;
    }
}

// ---------------------------------------------------------------------------
// K2: reduce partials -> per-channel scale/shift (deterministic, single block)
// ---------------------------------------------------------------------------
__global__ __launch_bounds__(1024)
void stats_kernel(const float* __restrict__ part,
                  const float* __restrict__ gamma,
                  const float* __restrict__ beta,
                  float* __restrict__ coef)
{
    const int t = threadIdx.x;
    const int j = t & 63;
    const int g = t >> 6;
    float s = 0.0f;
    for (int i = g; i < NBLK1; i += 16) s += part[(size_t)i * 64 + j];
    __shared__ float sm[16][64];
    sm[g][j] = s;
    __syncthreads();
    if (t < 64) {
        float tot = 0.0f;
#pragma unroll
        for (int r = 0; r < 16; r++) tot += sm[r][t];
        sm[0][t] = tot;
    }
    __syncthreads();
    if (t < 32) {
        const float invN  = 1.0f / (float)NPTS;
        const float mean  = sm[0][t] * invN;
        const float ex2   = sm[0][32 + t] * invN;
        const float var   = ex2 - mean * mean;
        const float scale = gamma[t] * rsqrtf(var + 1e-5f);
        coef[t]      = scale;
        coef[32 + t] = beta[t] - mean * scale;
    }
}

// ---------------------------------------------------------------------------
// K3: fused normalize + ReLU (vectorized float4)
// ---------------------------------------------------------------------------
__global__ __launch_bounds__(256)
void norm_kernel(const float* __restrict__ conv,
                 const float* __restrict__ coef,
                 float* __restrict__ out)
{
    const int i = blockIdx.x * 256 + threadIdx.x;
    if (i < TOTAL4) {
        float4 v = ((const float4*)conv)[i];
        const int q = i & 7;
        const float4 sc = ((const float4*)coef)[q];
        const float4 sh = ((const float4*)(coef + 32))[q];
        v.x = fmaxf(fmaf(v.x, sc.x, sh.x), 0.0f);
        v.y = fmaxf(fmaf(v.y, sc.y, sh.y), 0.0f);
        v.z = fmaxf(fmaf(v.z, sc.z, sh.z), 0.0f);
        v.w = fmaxf(fmaf(v.w, sc.w, sh.w), 0.0f);
        ((float4*)out)[i] = v;
    }
}

// ---------------------------------------------------------------------------
extern "C" void kernel_launch(void* const* d_in, const int* in_sizes, int n_in,
                              void* d_out, int out_size)
{
    const float* feat  = (const float*)d_in[0];
    const float* w     = (const float*)d_in[1];
    const float* gamma = (const float*)d_in[2];
    const float* beta  = (const float*)d_in[3];
    const int*   nidx  = (const int*)d_in[4];
    const void*  nmask = d_in[5];
    float* out = (float*)d_out;

    float* conv;  cudaGetSymbolAddress((void**)&conv,  g_conv);
    float* wT;    cudaGetSymbolAddress((void**)&wT,    g_wT);
    float* part;  cudaGetSymbolAddress((void**)&part,  g_part);
    float* coef;  cudaGetSymbolAddress((void**)&coef,  g_coef);

    detect_mask_kernel<<<1, 256>>>((const unsigned int*)nmask);
    transpose_w_kernel<<<(KTAPS * CIN * COUT + 255) / 256, 256>>>(w, wT);
    conv_kernel<<<NBLK1, BLOCK1>>>(feat, wT, nidx,
                                   (const unsigned char*)nmask,
                                   (const int*)nmask,
                                   conv, part);
    stats_kernel<<<1, 1024>>>(part, gamma, beta, coef);
    norm_kernel<<<NBLK3, 256>>>(conv, coef, out);
}

// round 12
// speedup vs baseline: 1.9560x; 1.9560x over previous
#include <cuda_runtime.h>
#include <cuda_bf16.h>

// Problem constants (fixed-shape problem)
#define NPTS   400000
#define CIN    32
#define COUT   32
#define KTAPS  27

#define BLOCK1 128          // 4 warps
#define WARPS1 4
#define PW     32           // points per warp
#define PTSBLK (WARPS1*PW)  // 128 points per block
#define NBLK1  (NPTS/PTSBLK) // 3125 exactly

#define TOTAL4 (NPTS*COUT/4)
#define NBLK3  (TOTAL4/256)

// Scratch (static device memory — no allocations)
__device__ float g_conv[(size_t)NPTS * COUT];
__device__ float g_part[(size_t)NBLK1 * 64];
__device__ float g_coef[64];
__device__ int   g_maskmode;   // 0 = uint8 mask, 1 = int32 mask

// ---------------------------------------------------------------------------
// K0: detect storage width of nbr_mask (int32 {0,1} vs packed uint8 bools)
// ---------------------------------------------------------------------------
__global__ void detect_mask_kernel(const unsigned int* __restrict__ m)
{
    __shared__ int found;
    if (threadIdx.x == 0) found = 0;
    __syncthreads();
    int f = 0;
    for (int i = threadIdx.x; i < 4096; i += blockDim.x)
        if (m[i] > 1u) f = 1;
    if (f) atomicOr(&found, 1);
    __syncthreads();
    if (threadIdx.x == 0) g_maskmode = found ? 0 : 1;
}

// ---------------------------------------------------------------------------
// K1: gather-conv with warp-cooperative row staging.
// lane = c_out; warp owns 32 points. Per tap k: ballot; then the warp stages
// ALL its valid rows for this tap into smem in one burst (<=8 rows/chunk,
// 4 lanes per row, 2 x LDG.128 each) -> ONE L2 latency exposure per tap,
// with the tap's weight loads issued under the same shadow. Compute reads
// rows via LDS.128 broadcast (29-cyc, conflict-free). __fns keeps the valid
// point enumeration warp-uniform (no per-point BSSY).
// ---------------------------------------------------------------------------
__global__ __launch_bounds__(BLOCK1)
void conv_kernel(const float* __restrict__ feat,
                 const float* __restrict__ wglob,
                 const int*   __restrict__ nidx,
                 const unsigned char* __restrict__ nmask8,
                 const int*   __restrict__ nmask32,
                 float* __restrict__ convout,
                 float* __restrict__ partials)
{
    // sacc[point_in_block][lane]: each thread exclusively owns column lane.
    __shared__ float sacc[PTSBLK * 32];
    __shared__ __align__(16) float4 fs[WARPS1][8][8];   // 8 staged rows/warp
    __shared__ float red[2][WARPS1][COUT];

    const int tid  = threadIdx.x;
    const int wid  = tid >> 5;
    const int lane = tid & 31;
    const int slot = lane >> 2;   // which staged row this lane helps load
    const int qc   = lane & 3;    // which float4 pair within the row
    const int n0   = blockIdx.x * PTSBLK + wid * PW;
    const int maskmode = g_maskmode;

#pragma unroll
    for (int p = 0; p < PW; p++) sacc[(wid * PW + p) * 32 + lane] = 0.0f;

    // meta for tap 0 (each lane carries one of the warp's 32 points)
    bool mv;
    int  idxv;
    {
        const size_t j = (size_t)(n0 + lane);
        mv   = maskmode ? (nmask32[j] != 0) : (nmask8[j] != 0);
        idxv = nidx[j];
    }

    for (int k = 0; k < KTAPS; k++) {
        const unsigned vm = __ballot_sync(0xffffffffu, mv);
        const int idxc = idxv;

        // prefetch meta for tap k+1
        if (k + 1 < KTAPS) {
            const size_t j = (size_t)(k + 1) * NPTS + (n0 + lane);
            mv   = maskmode ? (nmask32[j] != 0) : (nmask8[j] != 0);
            idxv = nidx[j];
        }

        if (vm == 0u) continue;   // warp-uniform

        unsigned rem = vm;
        bool first_chunk = true;
        float wr[CIN];

        while (rem) {
            const int nv = min(8, __popc(rem));

            // ---- stage: burst-load up to 8 valid rows into smem ----
            const unsigned pns = __fns(rem, 0, slot + 1);  // slot-th set bit
            const int gi = __shfl_sync(0xffffffffu, idxc, (int)(pns & 31u));
            if (slot < nv) {
                const float4* row = (const float4*)(feat + (size_t)gi * CIN);
                fs[wid][slot][qc]     = __ldg(row + qc);
                fs[wid][slot][qc + 4] = __ldg(row + qc + 4);
            }

            // weight column loads issue under the staging latency shadow
            if (first_chunk) {
                const float* wk = wglob + k * (CIN * COUT) + lane;
#pragma unroll
                for (int ci = 0; ci < CIN; ci++) wr[ci] = __ldg(wk + ci * COUT);
                first_chunk = false;
            }

            __syncwarp();

            // ---- compute: LDS.128 broadcast per row, 4-chain FMA tree ----
#pragma unroll 1
            for (int s = 0; s < nv; s++) {
                const int p = (int)__fns(rem, 0, s + 1);
                const float4* fq = &fs[wid][s][0];
                const float4 q0 = fq[0], q1 = fq[1], q2 = fq[2], q3 = fq[3];
                const float4 q4 = fq[4], q5 = fq[5], q6 = fq[6], q7 = fq[7];
                float t0 = 0.f, t1 = 0.f, t2 = 0.f, t3 = 0.f;
                t0 = fmaf(q0.x, wr[ 0], t0); t1 = fmaf(q0.y, wr[ 1], t1);
                t2 = fmaf(q0.z, wr[ 2], t2); t3 = fmaf(q0.w, wr[ 3], t3);
                t0 = fmaf(q1.x, wr[ 4], t0); t1 = fmaf(q1.y, wr[ 5], t1);
                t2 = fmaf(q1.z, wr[ 6], t2); t3 = fmaf(q1.w, wr[ 7], t3);
                t0 = fmaf(q2.x, wr[ 8], t0); t1 = fmaf(q2.y, wr[ 9], t1);
                t2 = fmaf(q2.z, wr[10], t2); t3 = fmaf(q2.w, wr[11], t3);
                t0 = fmaf(q3.x, wr[12], t0); t1 = fmaf(q3.y, wr[13], t1);
                t2 = fmaf(q3.z, wr[14], t2); t3 = fmaf(q3.w, wr[15], t3);
                t0 = fmaf(q4.x, wr[16], t0); t1 = fmaf(q4.y, wr[17], t1);
                t2 = fmaf(q4.z, wr[18], t2); t3 = fmaf(q4.w, wr[19], t3);
                t0 = fmaf(q5.x, wr[20], t0); t1 = fmaf(q5.y, wr[21], t1);
                t2 = fmaf(q5.z, wr[22], t2); t3 = fmaf(q5.w, wr[23], t3);
                t0 = fmaf(q6.x, wr[24], t0); t1 = fmaf(q6.y, wr[25], t1);
                t2 = fmaf(q6.z, wr[26], t2); t3 = fmaf(q6.w, wr[27], t3);
                t0 = fmaf(q7.x, wr[28], t0); t1 = fmaf(q7.y, wr[29], t1);
                t2 = fmaf(q7.z, wr[30], t2); t3 = fmaf(q7.w, wr[31], t3);
                const float dot = (t0 + t1) + (t2 + t3);
                sacc[(wid * PW + p) * 32 + lane] += dot;   // exclusive slot
            }
            __syncwarp();   // protect fs before next chunk overwrites

            // clear the nv consumed (lowest) bits
#pragma unroll 1
            for (int i = 0; i < nv; i++) rem &= rem - 1u;
        }
    }

    // write conv output (coalesced) + per-block partial sums for batchnorm
    float s = 0.0f, s2 = 0.0f;
#pragma unroll
    for (int p = 0; p < PW; p++) {
        const float v = sacc[(wid * PW + p) * 32 + lane];
        convout[(size_t)(n0 + p) * COUT + lane] = v;
        s  += v;
        s2 += v * v;
    }
    red[0][wid][lane] = s;
    red[1][wid][lane] = s2;
    __syncthreads();
    if (wid == 0) {
        float a = 0.0f, b = 0.0f;
#pragma unroll
        for (int w = 0; w < WARPS1; w++) { a += red[0][w][lane]; b += red[1][w][lane]; }
        partials[(size_t)blockIdx.x * 64 + lane]      = a;
        partials[(size_t)blockIdx.x * 64 + 32 + lane] = b;
    }
}

// ---------------------------------------------------------------------------
// K2: reduce partials -> per-channel scale/shift (deterministic, single block)
// ---------------------------------------------------------------------------
__global__ __launch_bounds__(1024)
void stats_kernel(const float* __restrict__ part,
                  const float* __restrict__ gamma,
                  const float* __restrict__ beta,
                  float* __restrict__ coef)
{
    const int t = threadIdx.x;
    const int j = t & 63;
    const int g = t >> 6;
    float s = 0.0f;
    for (int i = g; i < NBLK1; i += 16) s += part[(size_t)i * 64 + j];
    __shared__ float sm[16][64];
    sm[g][j] = s;
    __syncthreads();
    if (t < 64) {
        float tot = 0.0f;
#pragma unroll
        for (int r = 0; r < 16; r++) tot += sm[r][t];
        sm[0][t] = tot;
    }
    __syncthreads();
    if (t < 32) {
        const float invN  = 1.0f / (float)NPTS;
        const float mean  = sm[0][t] * invN;
        const float ex2   = sm[0][32 + t] * invN;
        const float var   = ex2 - mean * mean;
        const float scale = gamma[t] * rsqrtf(var + 1e-5f);
        coef[t]      = scale;
        coef[32 + t] = beta[t] - mean * scale;
    }
}

// ---------------------------------------------------------------------------
// K3: fused normalize + ReLU (vectorized float4)
// ---------------------------------------------------------------------------
__global__ __launch_bounds__(256)
void norm_kernel(const float* __restrict__ conv,
                 const float* __restrict__ coef,
                 float* __restrict__ out)
{
    const int i = blockIdx.x * 256 + threadIdx.x;
    if (i < TOTAL4) {
        float4 v = ((const float4*)conv)[i];
        const int q = i & 7;
        const float4 sc = ((const float4*)coef)[q];
        const float4 sh = ((const float4*)(coef + 32))[q];
        v.x = fmaxf(fmaf(v.x, sc.x, sh.x), 0.0f);
        v.y = fmaxf(fmaf(v.y, sc.y, sh.y), 0.0f);
        v.z = fmaxf(fmaf(v.z, sc.z, sh.z), 0.0f);
        v.w = fmaxf(fmaf(v.w, sc.w, sh.w), 0.0f);
        ((float4*)out)[i] = v;
    }
}

// ---------------------------------------------------------------------------
extern "C" void kernel_launch(void* const* d_in, const int* in_sizes, int n_in,
                              void* d_out, int out_size)
{
    const float* feat  = (const float*)d_in[0];
    const float* w     = (const float*)d_in[1];
    const float* gamma = (const float*)d_in[2];
    const float* beta  = (const float*)d_in[3];
    const int*   nidx  = (const int*)d_in[4];
    const void*  nmask = d_in[5];
    float* out = (float*)d_out;

    float* conv;  cudaGetSymbolAddress((void**)&conv,  g_conv);
    float* part;  cudaGetSymbolAddress((void**)&part,  g_part);
    float* coef;  cudaGetSymbolAddress((void**)&coef,  g_coef);

    detect_mask_kernel<<<1, 256>>>((const unsigned int*)nmask);
    conv_kernel<<<NBLK1, BLOCK1>>>(feat, w, nidx,
                                   (const unsigned char*)nmask,
                                   (const int*)nmask,
                                   conv, part);
    stats_kernel<<<1, 1024>>>(part, gamma, beta, coef);
    norm_kernel<<<NBLK3, 256>>>(conv, coef, out);
}